// round 5
// baseline (speedup 1.0000x reference)
#include <cuda_runtime.h>
#include <cuda_fp16.h>

// Problem constants (match reference)
#define NGRID 512
#define NB    10      // bond types
#define NM    16      // integrals
#define E_EDGES 2000000
#define N_NODES 500000

// Derived output offsets (floats)
#define OUT_OVL_OFF  (E_EDGES * NM)          // 32,000,000
#define OUT_NODE_OFF (2 * E_EDGES * NM)      // 64,000,000

// Combined fp16 table: row (b,g) = 64 B = [hop m0..15 | ovl m0..15] halfs.
// Total 10*512*32*2 = 320 KB. Interp math stays fp32.
__device__ __align__(128) __half g_tab[NB * NGRID * 32];

#define NTRANS (NB * NM * NGRID)   // 81920 elements per source table
#define E4     (E_EDGES * 4)       // 8,000,000 edge lanes

// ---------------------------------------------------------------------------
// Kernel 1: transpose + fp16 convert both tables into the combined layout.
// ---------------------------------------------------------------------------
__global__ void __launch_bounds__(256)
prep_kernel(const float* __restrict__ hop,
            const float* __restrict__ ovl) {
    int idx = blockIdx.x * blockDim.x + threadIdx.x;
    if (idx >= NTRANS) return;
    int g = idx & (NGRID - 1);
    int m = (idx >> 9) & (NM - 1);
    int b = idx / (NGRID * NM);
    int base = ((b << 9) + g) << 5;              // (b*512+g)*32 half index
    g_tab[base + m]      = __float2half(__ldg(hop + idx));
    g_tab[base + NM + m] = __float2half(__ldg(ovl + idx));
}

// ---------------------------------------------------------------------------
// Kernel 2: edges (4 lanes/edge) + nodes, one launch.
// Lane s in [0,4): loads 16 B (8 halfs) of row i0 and row i0+1 (2x LDG.128).
//   s=0: hop m0-7   s=1: hop m8-15   s=2: ovl m0-7   s=3: ovl m8-15
// Produces 8 fp32 outputs = two float4 stores forming ONE contiguous 32B
// sector per lane -> sector-perfect write stream. 8M threads total for edges.
// ---------------------------------------------------------------------------
__global__ void __launch_bounds__(256)
main_kernel(const float* __restrict__ rij,
            const int*   __restrict__ edge_type,
            const int*   __restrict__ atom_type,
            const float* __restrict__ onsiteE,
            float*       __restrict__ out) {
    int t = blockIdx.x * blockDim.x + threadIdx.x;

    if (t < E4) {
        int e = t >> 2;
        int s = t & 3;

        float r = __ldg(rij + e);
        int   b = __ldg(edge_type + e);

        const float DXf = (float)((10.0 - 1.0) / (double)(NGRID - 1));
        float tt = (r - 1.0f) / DXf;
        int i0 = (int)floorf(tt);
        i0 = min(max(i0, 0), NGRID - 2);
        float frac = tt - (float)i0;
        float w0 = 1.0f - frac;

        // uint4 (16B) units: 4 per 64B row. Row i0 base = (b*512+i0)*4.
        int row0 = (((b << 9) + i0) << 2) + s;
        const uint4* tab4 = (const uint4*)g_tab;
        uint4 d0 = __ldg(tab4 + row0);       // 8 halfs, row i0
        uint4 d1 = __ldg(tab4 + row0 + 4);   // 8 halfs, row i0+1

        float2 a0 = __half22float2(*reinterpret_cast<const __half2*>(&d0.x));
        float2 a1 = __half22float2(*reinterpret_cast<const __half2*>(&d0.y));
        float2 a2 = __half22float2(*reinterpret_cast<const __half2*>(&d0.z));
        float2 a3 = __half22float2(*reinterpret_cast<const __half2*>(&d0.w));
        float2 c0 = __half22float2(*reinterpret_cast<const __half2*>(&d1.x));
        float2 c1 = __half22float2(*reinterpret_cast<const __half2*>(&d1.y));
        float2 c2 = __half22float2(*reinterpret_cast<const __half2*>(&d1.z));
        float2 c3 = __half22float2(*reinterpret_cast<const __half2*>(&d1.w));

        float4 r0, r1;
        r0.x = a0.x * w0 + c0.x * frac;
        r0.y = a0.y * w0 + c0.y * frac;
        r0.z = a1.x * w0 + c1.x * frac;
        r0.w = a1.y * w0 + c1.y * frac;
        r1.x = a2.x * w0 + c2.x * frac;
        r1.y = a2.y * w0 + c2.y * frac;
        r1.z = a3.x * w0 + c3.x * frac;
        r1.w = a3.y * w0 + c3.y * frac;

        // Destination: s<2 -> hopping, s>=2 -> overlap; half-row h = s&1.
        // float4 index: arr_off/4 + e*4 + 2h  (and +1) -> one 32B sector/lane.
        int is_ovl = s >> 1;
        int h = s & 1;
        int dst4 = is_ovl * (OUT_OVL_OFF >> 2) + (e << 2) + (h << 1);
        float4* outv = (float4*)out;
        __stcs(outv + dst4, r0);
        __stcs(outv + dst4 + 1, r1);
    } else {
        int n = t - E4;
        if (n < N_NODES) {
            int at = __ldg(atom_type + n);
            float4 v = __ldg((const float4*)onsiteE + at);
            __stcs(((float4*)(out + OUT_NODE_OFF)) + n, v);
        }
    }
}

// ---------------------------------------------------------------------------
// Launch
// ---------------------------------------------------------------------------
extern "C" void kernel_launch(void* const* d_in, const int* in_sizes, int n_in,
                              void* d_out, int out_size) {
    const float* rij       = (const float*)d_in[0];
    const int*   edge_type = (const int*)d_in[1];
    const int*   atom_type = (const int*)d_in[2];
    const float* hop       = (const float*)d_in[3];
    const float* ovl       = (const float*)d_in[4];
    const float* onsiteE   = (const float*)d_in[5];
    float* out = (float*)d_out;

    // 1) build combined fp16 table
    {
        int blk = 256;
        prep_kernel<<<(NTRANS + blk - 1) / blk, blk>>>(hop, ovl);
    }
    // 2) edges + nodes
    {
        int total = E4 + N_NODES;                   // 8,500,000
        int blk = 256;
        main_kernel<<<(total + blk - 1) / blk, blk>>>(rij, edge_type,
                                                      atom_type, onsiteE, out);
    }
}

// round 6
// speedup vs baseline: 1.3493x; 1.3493x over previous
#include <cuda_runtime.h>
#include <cuda_fp16.h>

// Problem constants (match reference)
#define NGRID 512
#define NB    10      // bond types
#define NM    16      // integrals
#define E_EDGES 2000000
#define N_NODES 500000

// Derived output offsets (floats)
#define OUT_OVL_OFF  (E_EDGES * NM)          // 32,000,000
#define OUT_NODE_OFF (2 * E_EDGES * NM)      // 64,000,000

// Combined fp16 table: row (b,g) = 64 B = [hop m0..15 | ovl m0..15] halfs.
// Total 10*512*32*2 = 320 KB. Interp math stays fp32.
__device__ __align__(128) __half g_tab[NB * NGRID * 32];

#define NTRANS  (NB * NM * NGRID)     // 81920 elements per source table
#define NGROUPS (E_EDGES / 2)         // 1,000,000 edge pairs
#define ETHREADS (NGROUPS * 8)        // 8,000,000 edge threads

// ---------------------------------------------------------------------------
// Kernel 1: transpose + fp16 convert both tables into the combined layout.
// ---------------------------------------------------------------------------
__global__ void __launch_bounds__(256)
prep_kernel(const float* __restrict__ hop,
            const float* __restrict__ ovl) {
    int idx = blockIdx.x * blockDim.x + threadIdx.x;
    if (idx >= NTRANS) return;
    int g = idx & (NGRID - 1);
    int m = (idx >> 9) & (NM - 1);
    int b = idx / (NGRID * NM);
    int base = ((b << 9) + g) << 5;              // (b*512+g)*32 half index
    g_tab[base + m]      = __float2half(__ldg(hop + idx));
    g_tab[base + NM + m] = __float2half(__ldg(ovl + idx));
}

// ---------------------------------------------------------------------------
// Helper: interpolate one edge for lane-slot s (R4's proven access pattern).
//   gather: 2x LDG.64 from one 64B row each (4 distinct lines/warp/instr)
//   store : one float4 (lanes of an edge cover 2 contiguous lines per array)
// ---------------------------------------------------------------------------
__device__ __forceinline__ void edge_store(int e, int s, float w0, float frac,
                                           uint2 d0, uint2 d1,
                                           float* __restrict__ out) {
    float2 a01 = __half22float2(*reinterpret_cast<const __half2*>(&d0.x));
    float2 a23 = __half22float2(*reinterpret_cast<const __half2*>(&d0.y));
    float2 b01 = __half22float2(*reinterpret_cast<const __half2*>(&d1.x));
    float2 b23 = __half22float2(*reinterpret_cast<const __half2*>(&d1.y));

    float4 res;
    res.x = a01.x * w0 + b01.x * frac;
    res.y = a01.y * w0 + b01.y * frac;
    res.z = a23.x * w0 + b23.x * frac;
    res.w = a23.y * w0 + b23.y * frac;

    int is_ovl = s >> 2;
    int q = s & 3;
    int dst4 = is_ovl * (OUT_OVL_OFF >> 2) + (e << 2) + q;
    __stcs(((float4*)out) + dst4, res);
}

// ---------------------------------------------------------------------------
// Kernel 2: edges (8 lanes/edge, 2 edges/thread) + nodes, one launch.
// Thread t: group gpair = t>>3, slot s = t&7; edges e0=gpair, e1=gpair+1M.
// All 4 scalar loads + all 4 table gathers are issued before any consume ->
// MLP=4 on the latency-critical gathers (was 2 in R4).
// ---------------------------------------------------------------------------
__global__ void __launch_bounds__(256)
main_kernel(const float* __restrict__ rij,
            const int*   __restrict__ edge_type,
            const int*   __restrict__ atom_type,
            const float* __restrict__ onsiteE,
            float*       __restrict__ out) {
    int t = blockIdx.x * blockDim.x + threadIdx.x;

    if (t < ETHREADS) {
        int gp = t >> 3;
        int s  = t & 7;
        int e0 = gp;
        int e1 = gp + NGROUPS;

        // scalar loads (coalesced/broadcast) — all in flight
        float r0f = __ldg(rij + e0);
        float r1f = __ldg(rij + e1);
        int   b0  = __ldg(edge_type + e0);
        int   b1  = __ldg(edge_type + e1);

        const float DXf = (float)((10.0 - 1.0) / (double)(NGRID - 1));

        float tt0 = (r0f - 1.0f) / DXf;
        int i00 = min(max((int)floorf(tt0), 0), NGRID - 2);
        float frac0 = tt0 - (float)i00;
        float w00 = 1.0f - frac0;

        float tt1 = (r1f - 1.0f) / DXf;
        int i01 = min(max((int)floorf(tt1), 0), NGRID - 2);
        float frac1 = tt1 - (float)i01;
        float w01 = 1.0f - frac1;

        const uint2* tab2 = (const uint2*)g_tab;
        int row0 = (((b0 << 9) + i00) << 3) + s;
        int row1 = (((b1 << 9) + i01) << 3) + s;

        // all 4 table gathers in flight before any consume
        uint2 d00 = __ldg(tab2 + row0);
        uint2 d01 = __ldg(tab2 + row0 + 8);
        uint2 d10 = __ldg(tab2 + row1);
        uint2 d11 = __ldg(tab2 + row1 + 8);

        edge_store(e0, s, w00, frac0, d00, d01, out);
        edge_store(e1, s, w01, frac1, d10, d11, out);
    } else {
        int n = t - ETHREADS;
        if (n < N_NODES) {
            int at = __ldg(atom_type + n);
            float4 v = __ldg((const float4*)onsiteE + at);
            __stcs(((float4*)(out + OUT_NODE_OFF)) + n, v);
        }
    }
}

// ---------------------------------------------------------------------------
// Launch
// ---------------------------------------------------------------------------
extern "C" void kernel_launch(void* const* d_in, const int* in_sizes, int n_in,
                              void* d_out, int out_size) {
    const float* rij       = (const float*)d_in[0];
    const int*   edge_type = (const int*)d_in[1];
    const int*   atom_type = (const int*)d_in[2];
    const float* hop       = (const float*)d_in[3];
    const float* ovl       = (const float*)d_in[4];
    const float* onsiteE   = (const float*)d_in[5];
    float* out = (float*)d_out;

    // 1) build combined fp16 table
    {
        int blk = 256;
        prep_kernel<<<(NTRANS + blk - 1) / blk, blk>>>(hop, ovl);
    }
    // 2) edges + nodes
    {
        int total = ETHREADS + N_NODES;             // 8,500,000
        int blk = 256;
        main_kernel<<<(total + blk - 1) / blk, blk>>>(rij, edge_type,
                                                      atom_type, onsiteE, out);
    }
}